// round 14
// baseline (speedup 1.0000x reference)
#include <cuda_runtime.h>
#include <cstdint>

// PureTransformerVM: one-hot "neural ALU" collapsed to exact integer /
// piecewise-linear arithmetic.
//  - sum_byte softmax has exactly 3 output values {1, e^-50, e^-100}
//  - gates = one-hot(op_idx)
//  - div   = PWL seed + 2 Newton steps + round + correction
// R14 = R9 (best: 17.25us) + BIT-EXACT div-path strength reduction:
//  - exp2f(integer e) == 2^e  -> construct bits directly
//  - x / 2^e is exact         -> multiply by exactly-representable 2^-e
// (floorf(log2f()), PWL seed, Newton steps, rint, correction unchanged.)
// Saves ~25 warp-issues/row on the issue-heavy path with zero value change.

#define NROWS 32768
#define OUT_COLS 296   // 256 sum_byte + 39 gates + 1 div

// softmax off-values (fp32-rounded). e^-100 is a subnormal (27 * 2^-149).
#define E_M50  1.9287498479639178e-22f
#define E_M100 3.7835058536770485e-44f

// 256-bit streaming store, L2 evict_first: output self-evicts instead of
// churning the input stream (the policy that produced the best timed runs).
static __device__ __forceinline__ void stg_ef8(float* p, const float* r) {
    asm volatile("st.global.L2::evict_first.v8.b32 [%0], "
                 "{%1,%2,%3,%4,%5,%6,%7,%8};"
                 :: "l"(p),
                    "f"(r[0]), "f"(r[1]), "f"(r[2]), "f"(r[3]),
                    "f"(r[4]), "f"(r[5]), "f"(r[6]), "f"(r[7])
                 : "memory");
}

// one-hot argmax via dot-product with the column-index vector.
// products and sums are exact in fp32 (values 0/1 times integers < 256).
static __device__ __forceinline__ float dot_idx(float4 v, float c0) {
    return fmaf(v.x, c0,
           fmaf(v.y, c0 + 1.0f,
           fmaf(v.z, c0 + 2.0f,
                v.w * (c0 + 3.0f))));
}

__global__ __launch_bounds__(256)
void vm_kernel(const float4* __restrict__ a_oh,
               const float4* __restrict__ b_oh,
               const float4* __restrict__ op_oh,
               const float*  __restrict__ a_f,
               const float*  __restrict__ b_f,
               float* __restrict__ out)
{
    const int gtid = blockIdx.x * blockDim.x + threadIdx.x;
    const int row  = gtid >> 5;           // grid covers exactly NROWS rows
    const int lane = gtid & 31;

    // ---- Front-batched loads: 5 wide + 2 scalar loads in flight ---------
    const float4* pa = a_oh  + (size_t)row * 64;
    const float4* pb = b_oh  + (size_t)row * 64;
    const float4* po = op_oh + (size_t)row * 64;

    float4 va0 = pa[lane];
    float4 va1 = pa[lane + 32];
    float4 vb0 = pb[lane];
    float4 vb1 = pb[lane + 32];
    // op_idx < 39: only the first 40 floats (10 float4) can be hot.
    // Unpredicated clamped load (lanes >=10 broadcast group 9, zeroed below).
    float4 vo = po[min(lane, 9)];

    const float af = a_f[row];
    const float bf = b_f[row];

    // ---- Argmax: index dot-products (fma pipe), ONE packed warp reduce --
    const float c0 = (float)(lane << 2);
    const float ia_f = dot_idx(va0, c0) + dot_idx(va1, c0 + 128.0f);
    const float ib_f = dot_idx(vb0, c0) + dot_idx(vb1, c0 + 128.0f);
    const float io_f = (lane < 10) ? dot_idx(vo, c0) : 0.0f;

    // Exactly one lane holds each index; pack (ia+ib) + 1024*io (< 2^24,
    // integer-exact in fp32), one F2I + one REDUX.ADD for all three.
    const int packed = __reduce_add_sync(0xffffffffu,
                          (int)(ia_f + ib_f + 1024.0f * io_f));
    const int io   = packed >> 10;
    const int sab  = packed & 1023;

    // ---- sum_byte index: 8-bit add (carry lo->hi, hi carry dropped) -----
    const int sbyte = sab & 255;
    const int sh = sbyte >> 4;
    const int sl = sbyte & 15;

    // ---- div path: values BIT-IDENTICAL to round-1 kernel ---------------
    float sa = (af > 0.f) ? 1.f : ((af < 0.f) ? -1.f : 0.f);
    float sb = (bf > 0.f) ? 1.f : ((bf < 0.f) ? -1.f : 0.f);
    float sg = sa * sb;
    if (sg == 0.f) sg = 1.f;

    const float aa = fabsf(af);
    const float ba = fabsf(bf);

    // expo exactly as before (reference-matching rounding), then exact
    // power-of-two construction: exp2f(int e) == 2^e bit-for-bit, and
    // division by 2^e is exact == multiplication by 2^-e.
    const float expo = floorf(log2f(ba + 1e-10f));
    const int   ei   = (int)expo;                       // in [0, 7] here
    const float ip2  = __int_as_float((127 - ei) << 23); // exact 2^-e

    const float norm = fminf(fmaxf(ba * ip2, 0.5f), 0.9999f);

    int seg = (int)floorf((norm - 0.5f) * 128.0f);
    seg = max(0, min(63, seg));
    const float bpl   = 0.5f + (float)seg * 0.0078125f;
    const float vl    = 1.0f / bpl;
    const float vr    = 1.0f / (bpl + 0.0078125f);
    const float slope = (vr - vl) * 128.0f;
    float y = vl + slope * (norm - bpl);

    y = y * (2.0f - norm * y);
    y = y * (2.0f - norm * y);
    y = y * ip2;                       // exact (power of two), == y / 2^e

    const float result = aa * y;
    float cand = rintf(result);
    const float check = cand * ba;
    if (check > aa + 0.5f) cand -= 1.0f;
    const float divres = cand * sg;

    // ---- Write 296 floats = 37 x 32B per row, evict-first streaming -----
    // Main: lane writes columns [8*lane, 8*lane+8) of the sum_byte block.
    float* rowbase = out + (size_t)row * OUT_COLS;

    float w[8];
    {
        const int cb = lane << 3;          // first column of this lane's 32B
        const int hi = cb >> 4;            // hi nibble fixed across the 8
        #pragma unroll
        for (int e = 0; e < 8; e++) {
            const int c = cb + e;
            float v = ((hi == sh) || ((c & 15) == sl)) ? E_M50 : E_M100;
            w[e] = (c == sbyte) ? 1.0f : v;
        }
    }
    stg_ef8(rowbase + (lane << 3), w);

    // Tail: 40 floats (gates 0..38 + div) = 5 lanes x 32B.
    if (lane < 5) {
        const int g0 = lane << 3;          // gate index of element 0
        #pragma unroll
        for (int e = 0; e < 8; e++)
            w[e] = ((g0 + e) == io) ? 1.0f : 0.0f;
        if (lane == 4) w[7] = divres;      // column 295
        stg_ef8(rowbase + 256 + (lane << 3), w);
    }
}

extern "C" void kernel_launch(void* const* d_in, const int* in_sizes, int n_in,
                              void* d_out, int out_size)
{
    (void)in_sizes; (void)n_in; (void)out_size;
    const float4* a_oh  = (const float4*)d_in[0];
    const float4* b_oh  = (const float4*)d_in[1];
    const float4* op_oh = (const float4*)d_in[2];
    const float*  a_f   = (const float*)d_in[3];
    const float*  b_f   = (const float*)d_in[4];
    float* out = (float*)d_out;

    // one warp per row: 32768 warps = 4096 blocks x 256 threads
    vm_kernel<<<4096, 256>>>(a_oh, b_oh, op_oh, a_f, b_f, out);
}

// round 15
// speedup vs baseline: 1.0920x; 1.0920x over previous
#include <cuda_runtime.h>
#include <cstdint>

// PureTransformerVM: one-hot "neural ALU" collapsed to exact integer /
// piecewise-linear arithmetic.
//  - sum_byte softmax has exactly 3 output values {1, e^-50, e^-100}
//  - gates = one-hot(op_idx)
//  - div   = PWL seed + 2 Newton steps + round + correction (verbatim from
//            round-1 kernel, which matched the reference exactly)
// R15 = R9 byte-for-byte (best: 17.25us timed). Locked-in final config:
//     default-policy loads, 256-bit evict_first streaming stores, 1 row/warp,
//     packed single REDUX. Every deviation tested (R4/R7/R8/R10/R12/R14)
//     regressed — including bit-exact instruction reductions — because the
//     binding constraint is ptxas's load schedule, which R9 wins.

#define NROWS 32768
#define OUT_COLS 296   // 256 sum_byte + 39 gates + 1 div

// softmax off-values (fp32-rounded). e^-100 is a subnormal (27 * 2^-149).
#define E_M50  1.9287498479639178e-22f
#define E_M100 3.7835058536770485e-44f

// 256-bit streaming store, L2 evict_first: output self-evicts instead of
// churning the input stream (the policy that produced the best timed runs).
static __device__ __forceinline__ void stg_ef8(float* p, const float* r) {
    asm volatile("st.global.L2::evict_first.v8.b32 [%0], "
                 "{%1,%2,%3,%4,%5,%6,%7,%8};"
                 :: "l"(p),
                    "f"(r[0]), "f"(r[1]), "f"(r[2]), "f"(r[3]),
                    "f"(r[4]), "f"(r[5]), "f"(r[6]), "f"(r[7])
                 : "memory");
}

// one-hot argmax via dot-product with the column-index vector.
// products and sums are exact in fp32 (values 0/1 times integers < 256).
static __device__ __forceinline__ float dot_idx(float4 v, float c0) {
    return fmaf(v.x, c0,
           fmaf(v.y, c0 + 1.0f,
           fmaf(v.z, c0 + 2.0f,
                v.w * (c0 + 3.0f))));
}

__global__ __launch_bounds__(256)
void vm_kernel(const float4* __restrict__ a_oh,
               const float4* __restrict__ b_oh,
               const float4* __restrict__ op_oh,
               const float*  __restrict__ a_f,
               const float*  __restrict__ b_f,
               float* __restrict__ out)
{
    const int gtid = blockIdx.x * blockDim.x + threadIdx.x;
    const int row  = gtid >> 5;           // grid covers exactly NROWS rows
    const int lane = gtid & 31;

    // ---- Front-batched loads: 5 wide + 2 scalar loads in flight ---------
    const float4* pa = a_oh  + (size_t)row * 64;
    const float4* pb = b_oh  + (size_t)row * 64;
    const float4* po = op_oh + (size_t)row * 64;

    float4 va0 = pa[lane];
    float4 va1 = pa[lane + 32];
    float4 vb0 = pb[lane];
    float4 vb1 = pb[lane + 32];
    // op_idx < 39: only the first 40 floats (10 float4) can be hot.
    // Unpredicated clamped load (lanes >=10 broadcast group 9, zeroed below).
    float4 vo = po[min(lane, 9)];

    const float af = a_f[row];
    const float bf = b_f[row];

    // ---- Argmax: index dot-products (fma pipe), ONE packed warp reduce --
    const float c0 = (float)(lane << 2);
    const float ia_f = dot_idx(va0, c0) + dot_idx(va1, c0 + 128.0f);
    const float ib_f = dot_idx(vb0, c0) + dot_idx(vb1, c0 + 128.0f);
    const float io_f = (lane < 10) ? dot_idx(vo, c0) : 0.0f;

    // Exactly one lane holds each index; pack (ia+ib) + 1024*io (< 2^24,
    // integer-exact in fp32), one F2I + one REDUX.ADD for all three.
    const int packed = __reduce_add_sync(0xffffffffu,
                          (int)(ia_f + ib_f + 1024.0f * io_f));
    const int io   = packed >> 10;
    const int sab  = packed & 1023;

    // ---- sum_byte index: 8-bit add (carry lo->hi, hi carry dropped) -----
    const int sbyte = sab & 255;
    const int sh = sbyte >> 4;
    const int sl = sbyte & 15;

    // ---- div path: VERBATIM from round-1 kernel (matched exactly) -------
    float sa = (af > 0.f) ? 1.f : ((af < 0.f) ? -1.f : 0.f);
    float sb = (bf > 0.f) ? 1.f : ((bf < 0.f) ? -1.f : 0.f);
    float sg = sa * sb;
    if (sg == 0.f) sg = 1.f;

    const float aa = fabsf(af);
    const float ba = fabsf(bf);

    const float expo = floorf(log2f(ba + 1e-10f));
    const float p2   = exp2f(expo);
    const float norm = fminf(fmaxf(ba / p2, 0.5f), 0.9999f);

    int seg = (int)floorf((norm - 0.5f) * 128.0f);
    seg = max(0, min(63, seg));
    const float bpl   = 0.5f + (float)seg * 0.0078125f;
    const float vl    = 1.0f / bpl;
    const float vr    = 1.0f / (bpl + 0.0078125f);
    const float slope = (vr - vl) * 128.0f;
    float y = vl + slope * (norm - bpl);

    y = y * (2.0f - norm * y);
    y = y * (2.0f - norm * y);
    y = y / p2;

    const float result = aa * y;
    float cand = rintf(result);
    const float check = cand * ba;
    if (check > aa + 0.5f) cand -= 1.0f;
    const float divres = cand * sg;

    // ---- Write 296 floats = 37 x 32B per row, evict-first streaming -----
    // Main: lane writes columns [8*lane, 8*lane+8) of the sum_byte block.
    float* rowbase = out + (size_t)row * OUT_COLS;

    float w[8];
    {
        const int cb = lane << 3;          // first column of this lane's 32B
        const int hi = cb >> 4;            // hi nibble fixed across the 8
        #pragma unroll
        for (int e = 0; e < 8; e++) {
            const int c = cb + e;
            float v = ((hi == sh) || ((c & 15) == sl)) ? E_M50 : E_M100;
            w[e] = (c == sbyte) ? 1.0f : v;
        }
    }
    stg_ef8(rowbase + (lane << 3), w);

    // Tail: 40 floats (gates 0..38 + div) = 5 lanes x 32B.
    if (lane < 5) {
        const int g0 = lane << 3;          // gate index of element 0
        #pragma unroll
        for (int e = 0; e < 8; e++)
            w[e] = ((g0 + e) == io) ? 1.0f : 0.0f;
        if (lane == 4) w[7] = divres;      // column 295
        stg_ef8(rowbase + 256 + (lane << 3), w);
    }
}

extern "C" void kernel_launch(void* const* d_in, const int* in_sizes, int n_in,
                              void* d_out, int out_size)
{
    (void)in_sizes; (void)n_in; (void)out_size;
    const float4* a_oh  = (const float4*)d_in[0];
    const float4* b_oh  = (const float4*)d_in[1];
    const float4* op_oh = (const float4*)d_in[2];
    const float*  a_f   = (const float*)d_in[3];
    const float*  b_f   = (const float*)d_in[4];
    float* out = (float*)d_out;

    // one warp per row: 32768 warps = 4096 blocks x 256 threads
    vm_kernel<<<4096, 256>>>(a_oh, b_oh, op_oh, a_f, b_f, out);
}